// round 1
// baseline (speedup 1.0000x reference)
#include <cuda_runtime.h>

#define NN      50000      // nodes
#define NIN     128        // node in-dim
#define NOUT    64         // node out-dim
#define EIN     32         // edge feat dim
#define NE      400000     // undirected edges
#define ND      (2*NE)     // directed edges
#define ALPHA_L 0.2f
#define EPSV    1e-12f
#define NPART   256

// ---------------- scratch (device globals; no allocation allowed) -------------
__device__ float  g_hv[NN * NOUT];       // h_v
__device__ float  g_s1[NN];              // h_v . a[0:64]
__device__ float  g_s2[NN];              // h_v . a[64:128]
__device__ float  g_hn[NN];              // ||h_v||
__device__ float  g_attsum[NN];          // segment sum of exp(lr) by src
__device__ float  g_t[NE];               // edge_fts . a[128:160]
__device__ float  g_lr[ND];              // leaky_relu(logit) per directed edge
__device__ float  g_msg[NN * NOUT];      // segment sum of h_v[dst]*att_norm by src
__device__ double g_psum[NPART];         // variance partials
__device__ double g_psq[NPART];

// ---------------- k0: zero the accumulators -----------------------------------
__global__ void k0_zero() {
    int stride = gridDim.x * blockDim.x;
    int tid = blockIdx.x * blockDim.x + threadIdx.x;
    for (int i = tid; i < NN * NOUT; i += stride) g_msg[i] = 0.f;
    for (int i = tid; i < NN; i += stride)        g_attsum[i] = 0.f;
    if (tid < NPART) { g_psum[tid] = 0.0; g_psq[tid] = 0.0; }
}

// ---------------- k1: h_v = node_fts @ W + b ----------------------------------
// 256 threads, 16 nodes/block. Thread = (node-group ng in 0..3, out col c in 0..63),
// each thread computes 4 nodes' column c. W (32KB) + 16 node rows (8KB) in smem.
__global__ void k1_gemm(const float* __restrict__ nf,
                        const float* __restrict__ W,
                        const float* __restrict__ b) {
    __shared__ float Ws[NIN * NOUT];     // 8192 floats
    __shared__ float nfs[16 * NIN];      // 2048 floats
    int tid = threadIdx.x;
    int base = blockIdx.x * 16;

    for (int i = tid; i < (NIN * NOUT) / 4; i += 256)
        ((float4*)Ws)[i] = ((const float4*)W)[i];
    for (int i = tid; i < (16 * NIN) / 4; i += 256)
        ((float4*)nfs)[i] = ((const float4*)(nf + (long)base * NIN))[i];
    __syncthreads();

    int c = tid & 63;
    int ng = tid >> 6;                   // 0..3, each owns 4 nodes
    const float* nb = &nfs[ng * 4 * NIN];

    float a0 = 0.f, a1 = 0.f, a2 = 0.f, a3 = 0.f;
#pragma unroll 8
    for (int k = 0; k < NIN; k++) {
        float w = Ws[k * NOUT + c];
        a0 += nb[k]         * w;
        a1 += nb[NIN + k]   * w;
        a2 += nb[2*NIN + k] * w;
        a3 += nb[3*NIN + k] * w;
    }
    float bc = b[c];
    int v = base + ng * 4;
    g_hv[(long)v * NOUT + c]       = a0 + bc;
    g_hv[(long)(v+1) * NOUT + c]   = a1 + bc;
    g_hv[(long)(v+2) * NOUT + c]   = a2 + bc;
    g_hv[(long)(v+3) * NOUT + c]   = a3 + bc;
}

// ---------------- k1b: per-node scalars s1, s2, ||h_v|| ------------------------
__global__ void k1b_scalars(const float* __restrict__ a_node) {
    int w = (blockIdx.x * blockDim.x + threadIdx.x) >> 5;
    int l = threadIdx.x & 31;
    if (w >= NN) return;
    float2 h = ((const float2*)g_hv)[(long)w * 32 + l];
    float a1x = __ldg(&a_node[2*l]),      a1y = __ldg(&a_node[2*l+1]);
    float a2x = __ldg(&a_node[64 + 2*l]), a2y = __ldg(&a_node[64 + 2*l+1]);
    float s1 = h.x * a1x + h.y * a1y;
    float s2 = h.x * a2x + h.y * a2y;
    float sq = h.x * h.x + h.y * h.y;
#pragma unroll
    for (int o = 16; o; o >>= 1) {
        s1 += __shfl_down_sync(0xffffffffu, s1, o);
        s2 += __shfl_down_sync(0xffffffffu, s2, o);
        sq += __shfl_down_sync(0xffffffffu, sq, o);
    }
    if (l == 0) { g_s1[w] = s1; g_s2[w] = s2; g_hn[w] = sqrtf(sq); }
}

// ---------------- k2: t[e] = edge_fts[e] . a[128:160] --------------------------
__global__ void k2_edgedot(const float* __restrict__ ef,
                           const float* __restrict__ a_node) {
    int i = blockIdx.x * blockDim.x + threadIdx.x;
    if (i >= NE) return;
    const float4* e4 = (const float4*)(ef + (long)i * EIN);
    const float* a3 = a_node + 2 * NOUT;
    float s = 0.f;
#pragma unroll
    for (int q = 0; q < EIN / 4; q++) {
        float4 v = e4[q];
        s += v.x * __ldg(&a3[4*q])   + v.y * __ldg(&a3[4*q+1])
           + v.z * __ldg(&a3[4*q+2]) + v.w * __ldg(&a3[4*q+3]);
    }
    g_t[i] = s;
}

// directed-edge decode:
// e = edges.reshape(-1,2) on the flat (2*NE) buffer p: e[u] = (p[2u], p[2u+1]).
// eu = [e; e[:, ::-1]]: j<NE -> (p[2j], p[2j+1]); j>=NE -> swapped, u = j-NE.
__device__ __forceinline__ void decode(const int* __restrict__ p, int j,
                                       int& src, int& dst, int& u) {
    u = (j < NE) ? j : j - NE;
    int x = __ldg(&p[2*u]), y = __ldg(&p[2*u+1]);
    src = (j < NE) ? x : y;
    dst = (j < NE) ? y : x;
}

// ---------------- k3: lr + att segment-sum --------------------------------------
__global__ void k3_att(const int* __restrict__ p) {
    int j = blockIdx.x * blockDim.x + threadIdx.x;
    if (j >= ND) return;
    int src, dst, u;
    decode(p, j, src, dst, u);
    float logit = g_s1[src] + g_s2[dst] + g_t[u];
    float lr = (logit > 0.f) ? logit : ALPHA_L * logit;
    g_lr[j] = lr;
    atomicAdd(&g_attsum[src], __expf(lr));
}

// ---------------- k4: msg scatter + variance partials ---------------------------
#define EPW 8   // edges per warp
__global__ void k4_scatter(const int* __restrict__ p) {
    __shared__ float ssum[8], ssq[8];
    int warp = (blockIdx.x * blockDim.x + threadIdx.x) >> 5;
    int l = threadIdx.x & 31;
    long base = (long)warp * EPW;
    float lsum = 0.f, lsq = 0.f;
#pragma unroll
    for (int q = 0; q < EPW; q++) {
        long j = base + q;
        if (j >= ND) break;
        int src, dst, u;
        decode(p, (int)j, src, dst, u);
        float an = g_lr[j] - __logf(g_attsum[src]);
        float2 h = ((const float2*)g_hv)[(long)dst * 32 + l];
        atomicAdd(&g_msg[(long)src * NOUT + 2*l],     h.x * an);
        atomicAdd(&g_msg[(long)src * NOUT + 2*l + 1], h.y * an);
        lsum += an; lsq += an * an;   // identical on all lanes; lane 0 used
    }
    if (l == 0) { ssum[threadIdx.x >> 5] = lsum; ssq[threadIdx.x >> 5] = lsq; }
    __syncthreads();
    if (threadIdx.x == 0) {
        float bs = 0.f, bq = 0.f;
#pragma unroll
        for (int i = 0; i < 8; i++) { bs += ssum[i]; bq += ssq[i]; }
        atomicAdd(&g_psum[blockIdx.x & (NPART-1)], (double)bs);
        atomicAdd(&g_psq [blockIdx.x & (NPART-1)], (double)bq);
    }
}

// ---------------- k5: variance -> out[NN*128] ------------------------------------
__global__ void k5_var(float* __restrict__ out) {
    __shared__ double s[NPART], q[NPART];
    int t = threadIdx.x;
    s[t] = g_psum[t]; q[t] = g_psq[t];
    __syncthreads();
    for (int o = NPART/2; o; o >>= 1) {
        if (t < o) { s[t] += s[t+o]; q[t] += q[t+o]; }
        __syncthreads();
    }
    if (t == 0) {
        double E = (double)ND;
        double var = (q[0] - s[0]*s[0]/E) / (E - 1.0);
        out[(long)NN * 128] = (float)var;
    }
}

// ---------------- k6: final embed -------------------------------------------------
__global__ void k6_final(float* __restrict__ out, const float* __restrict__ scale) {
    int w = (blockIdx.x * blockDim.x + threadIdx.x) >> 5;
    int l = threadIdx.x & 31;
    if (w >= NN) return;
    float2 m = ((const float2*)g_msg)[(long)w * 32 + l];
    float sq = m.x*m.x + m.y*m.y;
#pragma unroll
    for (int o = 16; o; o >>= 1) sq += __shfl_down_sync(0xffffffffu, sq, o);
    sq = __shfl_sync(0xffffffffu, sq, 0);
    float r = g_hn[w] * __ldg(scale) / fmaxf(sqrtf(sq), EPSV);
    float2 h = ((const float2*)g_hv)[(long)w * 32 + l];
    float2* orow = (float2*)(out + (long)w * 128);
    orow[l]      = h;
    orow[32 + l] = make_float2(m.x * r, m.y * r);
}

// ---------------- launch -----------------------------------------------------------
extern "C" void kernel_launch(void* const* d_in, const int* in_sizes, int n_in,
                              void* d_out, int out_size) {
    const float* nf    = (const float*)d_in[0];  // node_fts [50000,128]
    const float* ef    = (const float*)d_in[1];  // edge_fts [400000,32]
    const int*   edges = (const int*)  d_in[2];  // edges [2,400000] (flat)
    const float* W     = (const float*)d_in[3];  // [128,64]
    const float* b     = (const float*)d_in[4];  // [64]
    const float* an    = (const float*)d_in[5];  // a_node [160]
    const float* scale = (const float*)d_in[6];  // scalar
    float* out = (float*)d_out;

    k0_zero   <<<512, 256>>>();
    k1_gemm   <<<NN/16, 256>>>(nf, W, b);
    k1b_scalars<<<(NN*32 + 255)/256, 256>>>(an);
    k2_edgedot<<<(NE + 255)/256, 256>>>(ef, an);
    k3_att    <<<(ND + 255)/256, 256>>>(edges);
    k4_scatter<<<(ND + 8*EPW*8 - 1)/(8*EPW), 256>>>(edges);   // 8 warps/block, 8 edges/warp
    k5_var    <<<1, NPART>>>(out);
    k6_final  <<<(NN*32 + 255)/256, 256>>>(out, scale);
}